// round 5
// baseline (speedup 1.0000x reference)
#include <cuda_runtime.h>
#include <cuda_bf16.h>
#include <cstdint>

// Problem constants
#define Bsz   256
#define Tsz   250
#define DIN   700
#define Hd    128
#define DOUT  20
#define KT    64            // k-tile
#define NKT   11            // 704 / 64

// Scratch
__device__ float g_h1[Tsz * Bsz * Hd];                 // h1_all[t][b][h]
__device__ __nv_bfloat16 g_Bh[NKT * 128 * KT];          // W1^T splits [kt][n][kk]
__device__ __nv_bfloat16 g_Bm[NKT * 128 * KT];
__device__ __nv_bfloat16 g_Bl[NKT * 128 * KT];

// ---- exact truncation split: a = h + m + l, each bf16-exact ---------------
__device__ __forceinline__ void bsplit(float a, float& h, float& m, float& l) {
    h = __uint_as_float(__float_as_uint(a) & 0xFFFF0000u);
    float r = a - h;                                    // exact
    m = __uint_as_float(__float_as_uint(r) & 0xFFFF0000u);
    l = r - m;                                          // exact, <=8 bits
}
__device__ __forceinline__ uint32_t hpack(float a, float b) {
    return __byte_perm(__float_as_uint(a), __float_as_uint(b), 0x7632);
}

// ---------------------------------------------------------------------------
// Prep: split W1 -> g_B{h,m,l}[kt][n][kk], zero pad k>=700
// ---------------------------------------------------------------------------
__global__ void prep_kernel(const float* __restrict__ W1)
{
    int idx = blockIdx.x * blockDim.x + threadIdx.x;
    if (idx >= NKT * 128 * KT) return;
    int kt = idx / (128 * KT);
    int r  = idx - kt * (128 * KT);
    int n  = r >> 6;
    int kk = r & 63;
    int k  = kt * KT + kk;
    float w = (k < DIN) ? W1[k * Hd + n] : 0.f;
    float h, m, l;
    bsplit(w, h, m, l);
    g_Bh[idx] = __float2bfloat16(h);
    g_Bm[idx] = __float2bfloat16(m);
    g_Bl[idx] = __float2bfloat16(l);
}

// ---------------------------------------------------------------------------
// mma.sync helpers (base sm_103 ISA)
// ---------------------------------------------------------------------------
__device__ __forceinline__ void mma_bf16(float* d, const uint32_t* a,
                                         const uint32_t* b) {
    asm volatile(
        "mma.sync.aligned.m16n8k16.row.col.f32.bf16.bf16.f32 "
        "{%0,%1,%2,%3}, {%4,%5,%6,%7}, {%8,%9}, {%0,%1,%2,%3};"
        : "+f"(d[0]), "+f"(d[1]), "+f"(d[2]), "+f"(d[3])
        : "r"(a[0]), "r"(a[1]), "r"(a[2]), "r"(a[3]), "r"(b[0]), "r"(b[1]));
}
__device__ __forceinline__ void ldsm4(uint32_t* r, uint32_t addr) {
    asm volatile("ldmatrix.sync.aligned.m8n8.x4.shared.b16 {%0,%1,%2,%3}, [%4];"
                 : "=r"(r[0]), "=r"(r[1]), "=r"(r[2]), "=r"(r[3]) : "r"(addr));
}
__device__ __forceinline__ uint32_t smem_u32(const void* p) {
    uint32_t a;
    asm("{ .reg .u64 t; cvta.to.shared.u64 t, %1; cvt.u32.u64 %0, t; }"
        : "=r"(a) : "l"(p));
    return a;
}

// smem byte offsets (rows are 64 bf16 = 128B, XOR-16 swizzle on (row&7))
#define GS_AH   0
#define GS_AM   16384
#define GS_AL   32768
#define GS_BH   49152
#define GS_BM   65536
#define GS_BL   81920
#define GS_BIAS 98304
#define GS_BYTES (GS_BIAS + 512)

// ---------------------------------------------------------------------------
// Kernel 1: h1_all = x @ W1 + b1 via bf16x3 (6-product, fp32-accurate) HMMA
// Now 2 CTAs/SM: co-resident CTA hides load/sync phases in the tensor pipe.
// ---------------------------------------------------------------------------
__global__ void __launch_bounds__(256, 2) gemm1_kernel(
    const float* __restrict__ x,
    const float* __restrict__ b1)
{
    extern __shared__ char smg[];
    const uint32_t sbase = smem_u32(smg);
    const int tid  = threadIdx.x;
    const int wid  = tid >> 5;
    const int lane = tid & 31;
    const int mw   = wid & 1;
    const int nw   = wid >> 1;
    const int m0   = blockIdx.x * 128;

    if (tid < 128) ((float*)(smg + GS_BIAS))[tid] = b1[tid];

    float acc[4][4][4];
    #pragma unroll
    for (int i = 0; i < 4; i++)
        #pragma unroll
        for (int j = 0; j < 4; j++)
            #pragma unroll
            for (int c = 0; c < 4; c++) acc[i][j][c] = 0.f;

    const int arow = tid >> 1;
    const int akh  = tid & 1;
    const float* xrow = x + (size_t)(m0 + arow) * DIN;
    const uint32_t aswz = (uint32_t)((arow & 7) << 4);
    const uint32_t abase = (uint32_t)(arow * 128);

    const int ra = (lane & 7) + ((lane >> 3) & 1) * 8;
    const int ka = (lane >> 4) * 8;
    const int rb = (lane & 7) + (lane >> 4) * 8;
    const int kbl = ((lane >> 3) & 1) * 8;
    const uint32_t lswz = (uint32_t)((lane & 7) << 4);

    for (int kt = 0; kt < NKT; kt++) {
        #pragma unroll
        for (int i = 0; i < 4; i++) {
            int kl = akh * 32 + i * 8;
            int gk = kt * KT + kl;
            float4 v0 = (gk <= DIN - 4) ? *(const float4*)(xrow + gk)
                                        : make_float4(0.f, 0.f, 0.f, 0.f);
            float4 v1 = (gk + 4 <= DIN - 4) ? *(const float4*)(xrow + gk + 4)
                                            : make_float4(0.f, 0.f, 0.f, 0.f);
            float h[8], m[8], l[8];
            bsplit(v0.x, h[0], m[0], l[0]); bsplit(v0.y, h[1], m[1], l[1]);
            bsplit(v0.z, h[2], m[2], l[2]); bsplit(v0.w, h[3], m[3], l[3]);
            bsplit(v1.x, h[4], m[4], l[4]); bsplit(v1.y, h[5], m[5], l[5]);
            bsplit(v1.z, h[6], m[6], l[6]); bsplit(v1.w, h[7], m[7], l[7]);
            uint32_t soff = abase + (((uint32_t)(kl * 2)) ^ aswz);
            *(uint4*)(smg + GS_AH + soff) =
                make_uint4(hpack(h[0],h[1]), hpack(h[2],h[3]),
                           hpack(h[4],h[5]), hpack(h[6],h[7]));
            *(uint4*)(smg + GS_AM + soff) =
                make_uint4(hpack(m[0],m[1]), hpack(m[2],m[3]),
                           hpack(m[4],m[5]), hpack(m[6],m[7]));
            *(uint4*)(smg + GS_AL + soff) =
                make_uint4(hpack(l[0],l[1]), hpack(l[2],l[3]),
                           hpack(l[4],l[5]), hpack(l[6],l[7]));
        }
        #pragma unroll
        for (int c = tid; c < 1024; c += 256) {
            int n  = c >> 3;
            int kc = c & 7;
            int src = kt * (128 * KT) + n * KT + kc * 8;
            uint32_t dst = (uint32_t)(n * 128)
                         + (((uint32_t)(kc * 16)) ^ ((uint32_t)((n & 7) << 4)));
            *(uint4*)(smg + GS_BH + dst) = *(const uint4*)(g_Bh + src);
            *(uint4*)(smg + GS_BM + dst) = *(const uint4*)(g_Bm + src);
            *(uint4*)(smg + GS_BL + dst) = *(const uint4*)(g_Bl + src);
        }
        __syncthreads();

        #pragma unroll
        for (int ks = 0; ks < 4; ks++) {
            const int kb = ks * 16;
            uint32_t ah[4][4], am[4][4], bh[4][2], bm[4][2];

            #pragma unroll
            for (int mt = 0; mt < 4; mt++) {
                uint32_t row = (uint32_t)(mw * 64 + mt * 16 + ra);
                uint32_t off = row * 128 + (((uint32_t)((kb + ka) * 2)) ^ lswz);
                ldsm4(ah[mt], sbase + GS_AH + off);
                ldsm4(am[mt], sbase + GS_AM + off);
            }
            #pragma unroll
            for (int g = 0; g < 2; g++) {
                uint32_t row = (uint32_t)(nw * 32 + g * 16 + rb);
                uint32_t off = row * 128 + (((uint32_t)((kb + kbl) * 2)) ^ lswz);
                uint32_t r4[4];
                ldsm4(r4, sbase + GS_BH + off);
                bh[g*2][0] = r4[0]; bh[g*2][1] = r4[1];
                bh[g*2+1][0] = r4[2]; bh[g*2+1][1] = r4[3];
                ldsm4(r4, sbase + GS_BM + off);
                bm[g*2][0] = r4[0]; bm[g*2][1] = r4[1];
                bm[g*2+1][0] = r4[2]; bm[g*2+1][1] = r4[3];
            }
            #pragma unroll
            for (int mt = 0; mt < 4; mt++)
                #pragma unroll
                for (int nt = 0; nt < 4; nt++) {
                    mma_bf16(acc[mt][nt], am[mt], bm[nt]);
                    mma_bf16(acc[mt][nt], ah[mt], bm[nt]);
                }
            #pragma unroll
            for (int g = 0; g < 2; g++) {
                uint32_t row = (uint32_t)(nw * 32 + g * 16 + rb);
                uint32_t off = row * 128 + (((uint32_t)((kb + kbl) * 2)) ^ lswz);
                uint32_t r4[4];
                ldsm4(r4, sbase + GS_BL + off);
                bm[g*2][0] = r4[0]; bm[g*2][1] = r4[1];
                bm[g*2+1][0] = r4[2]; bm[g*2+1][1] = r4[3];
            }
            #pragma unroll
            for (int mt = 0; mt < 4; mt++)
                #pragma unroll
                for (int nt = 0; nt < 4; nt++)
                    mma_bf16(acc[mt][nt], am[mt], bh[nt]);   // mh
            #pragma unroll
            for (int mt = 0; mt < 4; mt++) {
                uint32_t row = (uint32_t)(mw * 64 + mt * 16 + ra);
                uint32_t off = row * 128 + (((uint32_t)((kb + ka) * 2)) ^ lswz);
                ldsm4(am[mt], sbase + GS_AL + off);
            }
            #pragma unroll
            for (int mt = 0; mt < 4; mt++)
                #pragma unroll
                for (int nt = 0; nt < 4; nt++) {
                    mma_bf16(acc[mt][nt], ah[mt], bm[nt]);   // hl
                    mma_bf16(acc[mt][nt], am[mt], bh[nt]);   // lh
                    mma_bf16(acc[mt][nt], ah[mt], bh[nt]);   // hh
                }
        }
        __syncthreads();
    }

    // epilogue
    const float* sb1 = (const float*)(smg + GS_BIAS);
    const int r_lo = lane >> 2;
    const int c_lo = (lane & 3) * 2;
    #pragma unroll
    for (int mt = 0; mt < 4; mt++) {
        #pragma unroll
        for (int half = 0; half < 2; half++) {
            int mrow = m0 + mw * 64 + mt * 16 + r_lo + half * 8;
            int b = mrow / Tsz;
            int t = mrow - b * Tsz;
            float* orow = g_h1 + (size_t)t * (Bsz * Hd) + b * Hd;
            #pragma unroll
            for (int nt = 0; nt < 4; nt++) {
                int c = nw * 32 + nt * 8 + c_lo;
                float2 v;
                v.x = acc[mt][nt][half * 2 + 0] + sb1[c];
                v.y = acc[mt][nt][half * 2 + 1] + sb1[c + 1];
                *(float2*)(orow + c) = v;
            }
        }
    }
}

// ---------------------------------------------------------------------------
// Kernel 2: recurrent LIF, 512 threads/CTA, 2 samples/CTA,
// TWO threads per neuron (lane pairs) splitting the 4 mask words 2/2;
// partial u combined with one shfl_xor. 2 named barriers per step.
// ---------------------------------------------------------------------------
#define SM_W0   0
#define SM_W1   16384
#define SM_W2   32768
#define SM_W3   49152
#define SM_RCB1 51712
#define SM_B2C  51840
#define SM_WM1  51968
#define SM_WM2  51976
#define SM_FLOATS 51984
#define SM_BYTES  (SM_FLOATS * 4)

__global__ void __launch_bounds__(512, 1) rec_kernel(
    const float* __restrict__ rcW1, const float* __restrict__ rcb1,
    const float* __restrict__ W2,   const float* __restrict__ b2,
    const float* __restrict__ rcW2, const float* __restrict__ rcb2,
    const float* __restrict__ W3,   const float* __restrict__ b3,
    float* __restrict__ out)
{
    extern __shared__ float sm[];
    float* sW0   = sm + SM_W0;
    float* sW1   = sm + SM_W1;
    float* sW2   = sm + SM_W2;
    float* sW3   = sm + SM_W3;
    float* srcb1 = sm + SM_RCB1;
    float* sb2c  = sm + SM_B2C;
    unsigned* swm1 = (unsigned*)(sm + SM_WM1);
    unsigned* swm2 = (unsigned*)(sm + SM_WM2);

    const int tid = threadIdx.x;

    {
        const float4* a = (const float4*)rcW1;
        const float4* c = (const float4*)W2;
        const float4* d = (const float4*)rcW2;
        float4* o0 = (float4*)sW0; float4* o1 = (float4*)sW1; float4* o2 = (float4*)sW2;
        for (int i = tid; i < (Hd * Hd) / 4; i += 512) {
            o0[i] = a[i]; o1[i] = c[i]; o2[i] = d[i];
        }
    }
    for (int i = tid; i < Hd * DOUT; i += 512) sW3[i] = W3[i];
    if (tid < Hd) {
        srcb1[tid] = rcb1[tid];
        sb2c[tid]  = b2[tid] + rcb2[tid];
    }
    __syncthreads();

    const int hb   = tid >> 8;            // sample within CTA (warps 0-7 / 8-15)
    const int wl   = (tid >> 5) & 7;      // warp within sample
    const int lane = tid & 31;
    const int s    = lane & 1;            // subthread: mask words {2s, 2s+1}
    const int j    = wl * 16 + (lane >> 1);  // neuron index
    const int b    = blockIdx.x * 2 + hb;
    const int barid = 1 + hb;

    unsigned* wm1 = swm1 + hb * 4;
    unsigned* wm2 = swm2 + hb * 4;
    unsigned short* hm1 = (unsigned short*)wm1;
    unsigned short* hm2 = (unsigned short*)wm2;

    float v1 = 0.f, v2 = 0.f, acc = 0.f;
    unsigned m1[4] = {0u,0u,0u,0u};
    unsigned m2[4] = {0u,0u,0u,0u};

    const float* h1p = g_h1 + b * Hd + j;
    float h1v = h1p[0];

    const int q0 = 2 * s, q1 = 2 * s + 1;

    for (int t = 0; t < Tsz; t++) {
        float h1n = (t + 1 < Tsz) ? h1p[(size_t)(t + 1) * (Bsz * Hd)] : 0.f;

        // ---- phase 1: u1 = h1 + rcb1 + y1_old @ rcW1 ----
        float u = s ? 0.f : (h1v + srcb1[j]);
        {
            unsigned a0 = m1[q0], a1 = m1[q1];
            const float* p0 = sW0 + q0 * 32 * Hd + j;
            const float* p1 = sW0 + q1 * 32 * Hd + j;
            while (a0) { int i = __ffs(a0) - 1; a0 &= a0 - 1u; u += p0[i * Hd]; }
            while (a1) { int i = __ffs(a1) - 1; a1 &= a1 - 1u; u += p1[i * Hd]; }
        }
        u += __shfl_xor_sync(0xffffffffu, u, 1);
        v1 += (u - v1) * 0.5f;
        bool s1 = (v1 >= 1.0f);
        if (s1) v1 = 0.f;

        unsigned bal = __ballot_sync(0xffffffffu, s1) & 0x55555555u;
        bal = (bal | (bal >> 1)) & 0x33333333u;
        bal = (bal | (bal >> 2)) & 0x0F0F0F0Fu;
        bal = (bal | (bal >> 4)) & 0x00FF00FFu;
        bal = (bal | (bal >> 8)) & 0x0000FFFFu;
        if (lane == 0) hm1[wl] = (unsigned short)bal;
        asm volatile("bar.sync %0, 256;" :: "r"(barid) : "memory");
        m1[0] = wm1[0]; m1[1] = wm1[1]; m1[2] = wm1[2]; m1[3] = wm1[3];

        // ---- phase 2: u2 = b2 + rcb2 + y1_new @ W2 + y2_old @ rcW2 ----
        float u2 = s ? 0.f : sb2c[j];
        {
            unsigned a0 = m1[q0], a1 = m1[q1];
            const float* p0 = sW1 + q0 * 32 * Hd + j;
            const float* p1 = sW1 + q1 * 32 * Hd + j;
            while (a0) { int i = __ffs(a0) - 1; a0 &= a0 - 1u; u2 += p0[i * Hd]; }
            while (a1) { int i = __ffs(a1) - 1; a1 &= a1 - 1u; u2 += p1[i * Hd]; }
        }
        {
            unsigned a0 = m2[q0], a1 = m2[q1];
            const float* p0 = sW2 + q0 * 32 * Hd + j;
            const float* p1 = sW2 + q1 * 32 * Hd + j;
            while (a0) { int i = __ffs(a0) - 1; a0 &= a0 - 1u; u2 += p0[i * Hd]; }
            while (a1) { int i = __ffs(a1) - 1; a1 &= a1 - 1u; u2 += p1[i * Hd]; }
        }
        u2 += __shfl_xor_sync(0xffffffffu, u2, 1);
        v2 += (u2 - v2) * 0.5f;
        bool s2 = (v2 >= 1.0f);
        if (s2) v2 = 0.f;

        bal = __ballot_sync(0xffffffffu, s2) & 0x55555555u;
        bal = (bal | (bal >> 1)) & 0x33333333u;
        bal = (bal | (bal >> 2)) & 0x0F0F0F0Fu;
        bal = (bal | (bal >> 4)) & 0x00FF00FFu;
        bal = (bal | (bal >> 8)) & 0x0000FFFFu;
        if (lane == 0) hm2[wl] = (unsigned short)bal;
        asm volatile("bar.sync %0, 256;" :: "r"(barid) : "memory");
        m2[0] = wm2[0]; m2[1] = wm2[1]; m2[2] = wm2[2]; m2[3] = wm2[3];

        // ---- readout: acc += y2_new @ W3 (warps 0,1 of each sample) ----
        if (wl <= 1) {
            int jr = (j < DOUT) ? j : 0;
            float a = 0.f;
            unsigned a0 = m2[q0], a1 = m2[q1];
            const float* p0 = sW3 + q0 * 32 * DOUT + jr;
            const float* p1 = sW3 + q1 * 32 * DOUT + jr;
            while (a0) { int i = __ffs(a0) - 1; a0 &= a0 - 1u; a += p0[i * DOUT]; }
            while (a1) { int i = __ffs(a1) - 1; a1 &= a1 - 1u; a += p1[i * DOUT]; }
            a += __shfl_xor_sync(0xffffffffu, a, 1);
            acc += a;
        }
        h1v = h1n;
    }

    if (wl <= 1 && j < DOUT && s == 0)
        out[b * DOUT + j] = acc + (float)Tsz * b3[j];
}

// ---------------------------------------------------------------------------
// Launch
// ---------------------------------------------------------------------------
extern "C" void kernel_launch(void* const* d_in, const int* in_sizes, int n_in,
                              void* d_out, int out_size)
{
    const float* x    = (const float*)d_in[0];
    const float* W1   = (const float*)d_in[1];
    const float* b1   = (const float*)d_in[2];
    const float* rcW1 = (const float*)d_in[3];
    const float* rcb1 = (const float*)d_in[4];
    const float* W2   = (const float*)d_in[5];
    const float* b2   = (const float*)d_in[6];
    const float* rcW2 = (const float*)d_in[7];
    const float* rcb2 = (const float*)d_in[8];
    const float* W3   = (const float*)d_in[9];
    const float* b3   = (const float*)d_in[10];
    float* out = (float*)d_out;

    cudaFuncSetAttribute(gemm1_kernel,
                         cudaFuncAttributeMaxDynamicSharedMemorySize, GS_BYTES);
    cudaFuncSetAttribute(rec_kernel,
                         cudaFuncAttributeMaxDynamicSharedMemorySize, SM_BYTES);

    // 0) split W1 into bf16 h/m/l tiles
    prep_kernel<<<(NKT * 128 * KT + 255) / 256, 256>>>(W1);

    // 1) h1_all = x @ W1 + b1 (bf16x3 six-product HMMA, 2 CTAs/SM)
    gemm1_kernel<<<(Bsz * Tsz) / 128, 256, GS_BYTES>>>(x, b1);

    // 2) recurrent LIF loop (2 threads/neuron, shfl-combined)
    rec_kernel<<<Bsz / 2, 512, SM_BYTES>>>(rcW1, rcb1, W2, b2,
                                           rcW2, rcb2, W3, b3, out);
}

// round 6
// speedup vs baseline: 1.2555x; 1.2555x over previous
#include <cuda_runtime.h>
#include <cuda_bf16.h>
#include <cstdint>

// Problem constants
#define Bsz   256
#define Tsz   250
#define DIN   700
#define Hd    128
#define DOUT  20
#define KT    64            // k-tile
#define NKT   11            // 704 / 64

// Scratch
__device__ float g_h1[Tsz * Bsz * Hd];                 // h1_all[t][b][h]
__device__ __nv_bfloat16 g_Bh[NKT * 128 * KT];          // W1^T splits [kt][n][kk]
__device__ __nv_bfloat16 g_Bm[NKT * 128 * KT];
__device__ __nv_bfloat16 g_Bl[NKT * 128 * KT];

// ---- exact truncation split: a = h + m + l, each bf16-exact ---------------
__device__ __forceinline__ void bsplit(float a, float& h, float& m, float& l) {
    h = __uint_as_float(__float_as_uint(a) & 0xFFFF0000u);
    float r = a - h;                                    // exact
    m = __uint_as_float(__float_as_uint(r) & 0xFFFF0000u);
    l = r - m;                                          // exact, <=8 bits
}
__device__ __forceinline__ uint32_t hpack(float a, float b) {
    return __byte_perm(__float_as_uint(a), __float_as_uint(b), 0x7632);
}

// ---------------------------------------------------------------------------
// Prep: split W1 -> g_B{h,m,l}[kt][n][kk], zero pad k>=700
// ---------------------------------------------------------------------------
__global__ void prep_kernel(const float* __restrict__ W1)
{
    int idx = blockIdx.x * blockDim.x + threadIdx.x;
    if (idx >= NKT * 128 * KT) return;
    int kt = idx / (128 * KT);
    int r  = idx - kt * (128 * KT);
    int n  = r >> 6;
    int kk = r & 63;
    int k  = kt * KT + kk;
    float w = (k < DIN) ? W1[k * Hd + n] : 0.f;
    float h, m, l;
    bsplit(w, h, m, l);
    g_Bh[idx] = __float2bfloat16(h);
    g_Bm[idx] = __float2bfloat16(m);
    g_Bl[idx] = __float2bfloat16(l);
}

// ---------------------------------------------------------------------------
// mma.sync helpers (base sm_103 ISA)
// ---------------------------------------------------------------------------
__device__ __forceinline__ void mma_bf16(float* d, const uint32_t* a,
                                         const uint32_t* b) {
    asm volatile(
        "mma.sync.aligned.m16n8k16.row.col.f32.bf16.bf16.f32 "
        "{%0,%1,%2,%3}, {%4,%5,%6,%7}, {%8,%9}, {%0,%1,%2,%3};"
        : "+f"(d[0]), "+f"(d[1]), "+f"(d[2]), "+f"(d[3])
        : "r"(a[0]), "r"(a[1]), "r"(a[2]), "r"(a[3]), "r"(b[0]), "r"(b[1]));
}
__device__ __forceinline__ void ldsm4(uint32_t* r, uint32_t addr) {
    asm volatile("ldmatrix.sync.aligned.m8n8.x4.shared.b16 {%0,%1,%2,%3}, [%4];"
                 : "=r"(r[0]), "=r"(r[1]), "=r"(r[2]), "=r"(r[3]) : "r"(addr));
}
__device__ __forceinline__ uint32_t smem_u32(const void* p) {
    uint32_t a;
    asm("{ .reg .u64 t; cvta.to.shared.u64 t, %1; cvt.u32.u64 %0, t; }"
        : "=r"(a) : "l"(p));
    return a;
}
__device__ __forceinline__ void cp16(uint32_t dst, const void* src) {
    asm volatile("cp.async.cg.shared.global [%0], [%1], 16;"
                 :: "r"(dst), "l"(src));
}

// smem byte offsets: two full tile buffers (rows 64 bf16 = 128B, XOR-16 swz)
#define TB_AH   0
#define TB_AM   16384
#define TB_AL   32768
#define TB_BH   49152
#define TB_BM   65536
#define TB_BL   81920
#define TB_SIZE 98304
#define GS_BIAS (2 * TB_SIZE)
#define GS_BYTES (GS_BIAS + 512)          // 197,120 B (1 CTA/SM)

// ---------------------------------------------------------------------------
// Kernel 1: h1_all = x @ W1 + b1 via bf16x3 (6-product, fp32-accurate) HMMA.
// Double-buffered k-tiles: A(kt+1) staged in regs + cp.async B(kt+1) overlap
// the MMA phase of tile kt. One __syncthreads per k-tile. 1 CTA/SM (no spill).
// ---------------------------------------------------------------------------
__global__ void __launch_bounds__(256, 1) gemm1_kernel(
    const float* __restrict__ x,
    const float* __restrict__ b1)
{
    extern __shared__ char smg[];
    const uint32_t sbase = smem_u32(smg);
    const int tid  = threadIdx.x;
    const int wid  = tid >> 5;
    const int lane = tid & 31;
    const int mw   = wid & 1;
    const int nw   = wid >> 1;
    const int m0   = blockIdx.x * 128;

    if (tid < 128) ((float*)(smg + GS_BIAS))[tid] = b1[tid];

    float acc[4][4][4];
    #pragma unroll
    for (int i = 0; i < 4; i++)
        #pragma unroll
        for (int j = 0; j < 4; j++)
            #pragma unroll
            for (int c = 0; c < 4; c++) acc[i][j][c] = 0.f;

    const int arow = tid >> 1;
    const int akh  = tid & 1;
    const float* xrow = x + (size_t)(m0 + arow) * DIN;
    const uint32_t aswz = (uint32_t)((arow & 7) << 4);
    const uint32_t abase = (uint32_t)(arow * 128);

    const int ra = (lane & 7) + ((lane >> 3) & 1) * 8;
    const int ka = (lane >> 4) * 8;
    const int rb = (lane & 7) + (lane >> 4) * 8;
    const int kbl = ((lane >> 3) & 1) * 8;
    const uint32_t lswz = (uint32_t)((lane & 7) << 4);

    // B cp.async per-thread fixed mapping (4 chunks of 16B per split)
    int bn[4], bkc[4];
    uint32_t bdst[4];
    #pragma unroll
    for (int u = 0; u < 4; u++) {
        int c = tid + u * 256;
        bn[u]  = c >> 3;
        bkc[u] = c & 7;
        bdst[u] = (uint32_t)(bn[u] * 128)
                + (((uint32_t)(bkc[u] * 16)) ^ ((uint32_t)((bn[u] & 7) << 4)));
    }

    float4 va[8];   // staged A (32 floats)

    // ---- helpers as lambdas ----
    auto ldA = [&](int kt) {
        #pragma unroll
        for (int i = 0; i < 4; i++) {
            int kl = akh * 32 + i * 8;
            int gk = kt * KT + kl;
            va[i*2+0] = (gk <= DIN - 4) ? *(const float4*)(xrow + gk)
                                        : make_float4(0.f, 0.f, 0.f, 0.f);
            va[i*2+1] = (gk + 4 <= DIN - 4) ? *(const float4*)(xrow + gk + 4)
                                            : make_float4(0.f, 0.f, 0.f, 0.f);
        }
    };
    auto cpB = [&](int kt, uint32_t buf) {
        #pragma unroll
        for (int u = 0; u < 4; u++) {
            int src = kt * (128 * KT) + bn[u] * KT + bkc[u] * 8;
            cp16(buf + TB_BH + bdst[u], g_Bh + src);
            cp16(buf + TB_BM + bdst[u], g_Bm + src);
            cp16(buf + TB_BL + bdst[u], g_Bl + src);
        }
        asm volatile("cp.async.commit_group;" ::: "memory");
    };
    auto stsA = [&](char* bufp) {
        #pragma unroll
        for (int i = 0; i < 4; i++) {
            int kl = akh * 32 + i * 8;
            float4 v0 = va[i*2+0], v1 = va[i*2+1];
            float h[8], m[8], l[8];
            bsplit(v0.x, h[0], m[0], l[0]); bsplit(v0.y, h[1], m[1], l[1]);
            bsplit(v0.z, h[2], m[2], l[2]); bsplit(v0.w, h[3], m[3], l[3]);
            bsplit(v1.x, h[4], m[4], l[4]); bsplit(v1.y, h[5], m[5], l[5]);
            bsplit(v1.z, h[6], m[6], l[6]); bsplit(v1.w, h[7], m[7], l[7]);
            uint32_t soff = abase + (((uint32_t)(kl * 2)) ^ aswz);
            *(uint4*)(bufp + TB_AH + soff) =
                make_uint4(hpack(h[0],h[1]), hpack(h[2],h[3]),
                           hpack(h[4],h[5]), hpack(h[6],h[7]));
            *(uint4*)(bufp + TB_AM + soff) =
                make_uint4(hpack(m[0],m[1]), hpack(m[2],m[3]),
                           hpack(m[4],m[5]), hpack(m[6],m[7]));
            *(uint4*)(bufp + TB_AL + soff) =
                make_uint4(hpack(l[0],l[1]), hpack(l[2],l[3]),
                           hpack(l[4],l[5]), hpack(l[6],l[7]));
        }
    };

    // ---- prologue: tile 0 into buffer 0 ----
    ldA(0);
    cpB(0, sbase);
    stsA(smg);
    asm volatile("cp.async.wait_group 0;" ::: "memory");
    __syncthreads();

    for (int kt = 0; kt < NKT; kt++) {
        const uint32_t cbuf = (uint32_t)(kt & 1) * TB_SIZE;
        const uint32_t nbuf = (uint32_t)((kt + 1) & 1) * TB_SIZE;

        // kick off next tile's loads (overlap with MMA below)
        if (kt + 1 < NKT) {
            ldA(kt + 1);
            cpB(kt + 1, sbase + nbuf);
        }

        // ---- MMA on current buffer ----
        #pragma unroll
        for (int ks = 0; ks < 4; ks++) {
            const int kb = ks * 16;
            uint32_t ah[4][4], am[4][4], bh[4][2], bm[4][2];

            #pragma unroll
            for (int mt = 0; mt < 4; mt++) {
                uint32_t row = (uint32_t)(mw * 64 + mt * 16 + ra);
                uint32_t off = row * 128 + (((uint32_t)((kb + ka) * 2)) ^ lswz);
                ldsm4(ah[mt], sbase + cbuf + TB_AH + off);
                ldsm4(am[mt], sbase + cbuf + TB_AM + off);
            }
            #pragma unroll
            for (int g = 0; g < 2; g++) {
                uint32_t row = (uint32_t)(nw * 32 + g * 16 + rb);
                uint32_t off = row * 128 + (((uint32_t)((kb + kbl) * 2)) ^ lswz);
                uint32_t r4[4];
                ldsm4(r4, sbase + cbuf + TB_BH + off);
                bh[g*2][0] = r4[0]; bh[g*2][1] = r4[1];
                bh[g*2+1][0] = r4[2]; bh[g*2+1][1] = r4[3];
                ldsm4(r4, sbase + cbuf + TB_BM + off);
                bm[g*2][0] = r4[0]; bm[g*2][1] = r4[1];
                bm[g*2+1][0] = r4[2]; bm[g*2+1][1] = r4[3];
            }
            #pragma unroll
            for (int mt = 0; mt < 4; mt++)
                #pragma unroll
                for (int nt = 0; nt < 4; nt++) {
                    mma_bf16(acc[mt][nt], am[mt], bm[nt]);   // mm
                    mma_bf16(acc[mt][nt], ah[mt], bm[nt]);   // hm
                }
            #pragma unroll
            for (int g = 0; g < 2; g++) {
                uint32_t row = (uint32_t)(nw * 32 + g * 16 + rb);
                uint32_t off = row * 128 + (((uint32_t)((kb + kbl) * 2)) ^ lswz);
                uint32_t r4[4];
                ldsm4(r4, sbase + cbuf + TB_BL + off);
                bm[g*2][0] = r4[0]; bm[g*2][1] = r4[1];
                bm[g*2+1][0] = r4[2]; bm[g*2+1][1] = r4[3];
            }
            #pragma unroll
            for (int mt = 0; mt < 4; mt++)
                #pragma unroll
                for (int nt = 0; nt < 4; nt++)
                    mma_bf16(acc[mt][nt], am[mt], bh[nt]);   // mh
            #pragma unroll
            for (int mt = 0; mt < 4; mt++) {
                uint32_t row = (uint32_t)(mw * 64 + mt * 16 + ra);
                uint32_t off = row * 128 + (((uint32_t)((kb + ka) * 2)) ^ lswz);
                ldsm4(am[mt], sbase + cbuf + TB_AL + off);
            }
            #pragma unroll
            for (int mt = 0; mt < 4; mt++)
                #pragma unroll
                for (int nt = 0; nt < 4; nt++) {
                    mma_bf16(acc[mt][nt], ah[mt], bm[nt]);   // hl
                    mma_bf16(acc[mt][nt], am[mt], bh[nt]);   // lh
                    mma_bf16(acc[mt][nt], ah[mt], bh[nt]);   // hh
                }
        }

        // ---- finish next tile: split+store A, wait B arrival, sync ----
        if (kt + 1 < NKT) {
            stsA(smg + nbuf);
            asm volatile("cp.async.wait_group 0;" ::: "memory");
            __syncthreads();
        }
    }

    // epilogue
    const float* sb1 = (const float*)(smg + GS_BIAS);
    const int r_lo = lane >> 2;
    const int c_lo = (lane & 3) * 2;
    #pragma unroll
    for (int mt = 0; mt < 4; mt++) {
        #pragma unroll
        for (int half = 0; half < 2; half++) {
            int mrow = m0 + mw * 64 + mt * 16 + r_lo + half * 8;
            int b = mrow / Tsz;
            int t = mrow - b * Tsz;
            float* orow = g_h1 + (size_t)t * (Bsz * Hd) + b * Hd;
            #pragma unroll
            for (int nt = 0; nt < 4; nt++) {
                int c = nw * 32 + nt * 8 + c_lo;
                float2 v;
                v.x = acc[mt][nt][half * 2 + 0] + sb1[c];
                v.y = acc[mt][nt][half * 2 + 1] + sb1[c + 1];
                *(float2*)(orow + c) = v;
            }
        }
    }
}

// ---------------------------------------------------------------------------
// Kernel 2: persistent recurrent LIF loop (reverted to R4: 137us known-good)
// ---------------------------------------------------------------------------
#define SM_W0   0
#define SM_W1   16384
#define SM_W2   32768
#define SM_W3   49152
#define SM_RCB1 51712
#define SM_B2C  51840
#define SM_WM1  51968
#define SM_WM2  51976
#define SM_FLOATS 51984
#define SM_BYTES  (SM_FLOATS * 4)

__global__ void __launch_bounds__(256, 1) rec_kernel(
    const float* __restrict__ rcW1, const float* __restrict__ rcb1,
    const float* __restrict__ W2,   const float* __restrict__ b2,
    const float* __restrict__ rcW2, const float* __restrict__ rcb2,
    const float* __restrict__ W3,   const float* __restrict__ b3,
    float* __restrict__ out)
{
    extern __shared__ float sm[];
    float* sW0   = sm + SM_W0;
    float* sW1   = sm + SM_W1;
    float* sW2   = sm + SM_W2;
    float* sW3   = sm + SM_W3;
    float* srcb1 = sm + SM_RCB1;
    float* sb2c  = sm + SM_B2C;
    unsigned* swm1 = (unsigned*)(sm + SM_WM1);
    unsigned* swm2 = (unsigned*)(sm + SM_WM2);

    const int tid = threadIdx.x;

    {
        const float4* a = (const float4*)rcW1;
        const float4* c = (const float4*)W2;
        const float4* d = (const float4*)rcW2;
        float4* o0 = (float4*)sW0; float4* o1 = (float4*)sW1; float4* o2 = (float4*)sW2;
        for (int i = tid; i < (Hd * Hd) / 4; i += 256) {
            o0[i] = a[i]; o1[i] = c[i]; o2[i] = d[i];
        }
    }
    for (int i = tid; i < Hd * DOUT; i += 256) sW3[i] = W3[i];
    if (tid < Hd) {
        srcb1[tid] = rcb1[tid];
        sb2c[tid]  = b2[tid] + rcb2[tid];
    }
    __syncthreads();

    const int hb   = tid >> 7;
    const int j    = tid & 127;
    const int b    = blockIdx.x * 2 + hb;
    const int lane = tid & 31;
    const int w    = (tid >> 5) & 3;
    const int barid = 1 + hb;

    unsigned* wm1 = swm1 + hb * 4;
    unsigned* wm2 = swm2 + hb * 4;

    float v1 = 0.f, v2 = 0.f, acc = 0.f;
    unsigned m1[4] = {0u, 0u, 0u, 0u};
    unsigned m2[4] = {0u, 0u, 0u, 0u};

    const float* h1p = g_h1 + b * Hd + j;
    float h1v = h1p[0];

    for (int t = 0; t < Tsz; t++) {
        float h1n = (t + 1 < Tsz) ? h1p[(size_t)(t + 1) * (Bsz * Hd)] : 0.f;

        float u = h1v + srcb1[j];
        #pragma unroll
        for (int q = 0; q < 4; q++) {
            unsigned mm = m1[q];
            const float* wp = sW0 + q * 32 * Hd + j;
            while (mm) {
                int i = __ffs(mm) - 1; mm &= mm - 1u;
                u += wp[i * Hd];
            }
        }
        v1 += (u - v1) * 0.5f;
        bool s1 = (v1 >= 1.0f);
        if (s1) v1 = 0.f;

        unsigned bal = __ballot_sync(0xffffffffu, s1);
        if (lane == 0) wm1[w] = bal;
        asm volatile("bar.sync %0, 128;" :: "r"(barid) : "memory");
        m1[0] = wm1[0]; m1[1] = wm1[1]; m1[2] = wm1[2]; m1[3] = wm1[3];

        float u2 = sb2c[j];
        #pragma unroll
        for (int q = 0; q < 4; q++) {
            unsigned mm = m1[q];
            const float* wp = sW1 + q * 32 * Hd + j;
            while (mm) {
                int i = __ffs(mm) - 1; mm &= mm - 1u;
                u2 += wp[i * Hd];
            }
        }
        #pragma unroll
        for (int q = 0; q < 4; q++) {
            unsigned mm = m2[q];
            const float* wp = sW2 + q * 32 * Hd + j;
            while (mm) {
                int i = __ffs(mm) - 1; mm &= mm - 1u;
                u2 += wp[i * Hd];
            }
        }
        v2 += (u2 - v2) * 0.5f;
        bool s2 = (v2 >= 1.0f);
        if (s2) v2 = 0.f;

        bal = __ballot_sync(0xffffffffu, s2);
        if (lane == 0) wm2[w] = bal;
        asm volatile("bar.sync %0, 128;" :: "r"(barid) : "memory");
        m2[0] = wm2[0]; m2[1] = wm2[1]; m2[2] = wm2[2]; m2[3] = wm2[3];

        if (j < DOUT) {
            float a = 0.f;
            #pragma unroll
            for (int q = 0; q < 4; q++) {
                unsigned mm = m2[q];
                const float* wp = sW3 + q * 32 * DOUT + j;
                while (mm) {
                    int i = __ffs(mm) - 1; mm &= mm - 1u;
                    a += wp[i * DOUT];
                }
            }
            acc += a;
        }
        h1v = h1n;
    }

    if (j < DOUT)
        out[b * DOUT + j] = acc + (float)Tsz * b3[j];
}

// ---------------------------------------------------------------------------
// Launch
// ---------------------------------------------------------------------------
extern "C" void kernel_launch(void* const* d_in, const int* in_sizes, int n_in,
                              void* d_out, int out_size)
{
    const float* x    = (const float*)d_in[0];
    const float* W1   = (const float*)d_in[1];
    const float* b1   = (const float*)d_in[2];
    const float* rcW1 = (const float*)d_in[3];
    const float* rcb1 = (const float*)d_in[4];
    const float* W2   = (const float*)d_in[5];
    const float* b2   = (const float*)d_in[6];
    const float* rcW2 = (const float*)d_in[7];
    const float* rcb2 = (const float*)d_in[8];
    const float* W3   = (const float*)d_in[9];
    const float* b3   = (const float*)d_in[10];
    float* out = (float*)d_out;

    cudaFuncSetAttribute(gemm1_kernel,
                         cudaFuncAttributeMaxDynamicSharedMemorySize, GS_BYTES);
    cudaFuncSetAttribute(rec_kernel,
                         cudaFuncAttributeMaxDynamicSharedMemorySize, SM_BYTES);

    // 0) split W1 into bf16 h/m/l tiles
    prep_kernel<<<(NKT * 128 * KT + 255) / 256, 256>>>(W1);

    // 1) h1_all = x @ W1 + b1 (bf16x3 HMMA, double-buffered pipeline)
    gemm1_kernel<<<(Bsz * Tsz) / 128, 256, GS_BYTES>>>(x, b1);

    // 2) recurrent LIF loop (reverted to known-good 137us version)
    rec_kernel<<<Bsz / 2, 256, SM_BYTES>>>(rcW1, rcb1, W2, b2,
                                           rcW2, rcb2, W3, b3, out);
}

// round 7
// speedup vs baseline: 1.2667x; 1.0089x over previous
#include <cuda_runtime.h>
#include <cuda_bf16.h>
#include <cstdint>

// Problem constants
#define Bsz   256
#define Tsz   250
#define DIN   700
#define Hd    128
#define DOUT  20
#define KT    64            // k-tile
#define NKT   11            // 704 / 64

// Scratch
__device__ float g_h1[Tsz * Bsz * Hd];                 // h1_all[t][b][h]
__device__ __nv_bfloat16 g_Bh[NKT * 128 * KT];          // W1^T splits [kt][n][kk]
__device__ __nv_bfloat16 g_Bm[NKT * 128 * KT];
__device__ __nv_bfloat16 g_Bl[NKT * 128 * KT];

// ---- exact truncation split: a = h + m + l, each bf16-exact ---------------
__device__ __forceinline__ void bsplit(float a, float& h, float& m, float& l) {
    h = __uint_as_float(__float_as_uint(a) & 0xFFFF0000u);
    float r = a - h;                                    // exact
    m = __uint_as_float(__float_as_uint(r) & 0xFFFF0000u);
    l = r - m;                                          // exact, <=8 bits
}
__device__ __forceinline__ uint32_t hpack(float a, float b) {
    return __byte_perm(__float_as_uint(a), __float_as_uint(b), 0x7632);
}

// ---------------------------------------------------------------------------
// Prep: split W1 -> g_B{h,m,l}[kt][n][kk], zero pad k>=700
// ---------------------------------------------------------------------------
__global__ void prep_kernel(const float* __restrict__ W1)
{
    int idx = blockIdx.x * blockDim.x + threadIdx.x;
    if (idx >= NKT * 128 * KT) return;
    int kt = idx / (128 * KT);
    int r  = idx - kt * (128 * KT);
    int n  = r >> 6;
    int kk = r & 63;
    int k  = kt * KT + kk;
    float w = (k < DIN) ? W1[k * Hd + n] : 0.f;
    float h, m, l;
    bsplit(w, h, m, l);
    g_Bh[idx] = __float2bfloat16(h);
    g_Bm[idx] = __float2bfloat16(m);
    g_Bl[idx] = __float2bfloat16(l);
}

// ---------------------------------------------------------------------------
// mma.sync helpers (base sm_103 ISA)
// ---------------------------------------------------------------------------
__device__ __forceinline__ void mma_bf16(float* d, const uint32_t* a,
                                         const uint32_t* b) {
    asm volatile(
        "mma.sync.aligned.m16n8k16.row.col.f32.bf16.bf16.f32 "
        "{%0,%1,%2,%3}, {%4,%5,%6,%7}, {%8,%9}, {%0,%1,%2,%3};"
        : "+f"(d[0]), "+f"(d[1]), "+f"(d[2]), "+f"(d[3])
        : "r"(a[0]), "r"(a[1]), "r"(a[2]), "r"(a[3]), "r"(b[0]), "r"(b[1]));
}
__device__ __forceinline__ void ldsm4(uint32_t* r, uint32_t addr) {
    asm volatile("ldmatrix.sync.aligned.m8n8.x4.shared.b16 {%0,%1,%2,%3}, [%4];"
                 : "=r"(r[0]), "=r"(r[1]), "=r"(r[2]), "=r"(r[3]) : "r"(addr));
}
__device__ __forceinline__ uint32_t smem_u32(const void* p) {
    uint32_t a;
    asm("{ .reg .u64 t; cvta.to.shared.u64 t, %1; cvt.u32.u64 %0, t; }"
        : "=r"(a) : "l"(p));
    return a;
}
__device__ __forceinline__ void cp16(uint32_t dst, const void* src) {
    asm volatile("cp.async.cg.shared.global [%0], [%1], 16;"
                 :: "r"(dst), "l"(src));
}

// smem byte offsets: two full tile buffers (rows 64 bf16 = 128B, XOR-16 swz)
#define TB_AH   0
#define TB_AM   16384
#define TB_AL   32768
#define TB_BH   49152
#define TB_BM   65536
#define TB_BL   81920
#define TB_SIZE 98304
#define GS_BIAS (2 * TB_SIZE)
#define GS_BYTES (GS_BIAS + 512)          // 197,120 B (1 CTA/SM)

// ---------------------------------------------------------------------------
// Kernel 1: h1_all = x @ W1 + b1 via bf16x3 (6-product, fp32-accurate) HMMA.
// Double-buffered k-tiles (unchanged from R6: 198us known-good).
// ---------------------------------------------------------------------------
__global__ void __launch_bounds__(256, 1) gemm1_kernel(
    const float* __restrict__ x,
    const float* __restrict__ b1)
{
    extern __shared__ char smg[];
    const uint32_t sbase = smem_u32(smg);
    const int tid  = threadIdx.x;
    const int wid  = tid >> 5;
    const int lane = tid & 31;
    const int mw   = wid & 1;
    const int nw   = wid >> 1;
    const int m0   = blockIdx.x * 128;

    if (tid < 128) ((float*)(smg + GS_BIAS))[tid] = b1[tid];

    float acc[4][4][4];
    #pragma unroll
    for (int i = 0; i < 4; i++)
        #pragma unroll
        for (int j = 0; j < 4; j++)
            #pragma unroll
            for (int c = 0; c < 4; c++) acc[i][j][c] = 0.f;

    const int arow = tid >> 1;
    const int akh  = tid & 1;
    const float* xrow = x + (size_t)(m0 + arow) * DIN;
    const uint32_t aswz = (uint32_t)((arow & 7) << 4);
    const uint32_t abase = (uint32_t)(arow * 128);

    const int ra = (lane & 7) + ((lane >> 3) & 1) * 8;
    const int ka = (lane >> 4) * 8;
    const int rb = (lane & 7) + (lane >> 4) * 8;
    const int kbl = ((lane >> 3) & 1) * 8;
    const uint32_t lswz = (uint32_t)((lane & 7) << 4);

    int bn[4], bkc[4];
    uint32_t bdst[4];
    #pragma unroll
    for (int u = 0; u < 4; u++) {
        int c = tid + u * 256;
        bn[u]  = c >> 3;
        bkc[u] = c & 7;
        bdst[u] = (uint32_t)(bn[u] * 128)
                + (((uint32_t)(bkc[u] * 16)) ^ ((uint32_t)((bn[u] & 7) << 4)));
    }

    float4 va[8];

    auto ldA = [&](int kt) {
        #pragma unroll
        for (int i = 0; i < 4; i++) {
            int kl = akh * 32 + i * 8;
            int gk = kt * KT + kl;
            va[i*2+0] = (gk <= DIN - 4) ? *(const float4*)(xrow + gk)
                                        : make_float4(0.f, 0.f, 0.f, 0.f);
            va[i*2+1] = (gk + 4 <= DIN - 4) ? *(const float4*)(xrow + gk + 4)
                                            : make_float4(0.f, 0.f, 0.f, 0.f);
        }
    };
    auto cpB = [&](int kt, uint32_t buf) {
        #pragma unroll
        for (int u = 0; u < 4; u++) {
            int src = kt * (128 * KT) + bn[u] * KT + bkc[u] * 8;
            cp16(buf + TB_BH + bdst[u], g_Bh + src);
            cp16(buf + TB_BM + bdst[u], g_Bm + src);
            cp16(buf + TB_BL + bdst[u], g_Bl + src);
        }
        asm volatile("cp.async.commit_group;" ::: "memory");
    };
    auto stsA = [&](char* bufp) {
        #pragma unroll
        for (int i = 0; i < 4; i++) {
            int kl = akh * 32 + i * 8;
            float4 v0 = va[i*2+0], v1 = va[i*2+1];
            float h[8], m[8], l[8];
            bsplit(v0.x, h[0], m[0], l[0]); bsplit(v0.y, h[1], m[1], l[1]);
            bsplit(v0.z, h[2], m[2], l[2]); bsplit(v0.w, h[3], m[3], l[3]);
            bsplit(v1.x, h[4], m[4], l[4]); bsplit(v1.y, h[5], m[5], l[5]);
            bsplit(v1.z, h[6], m[6], l[6]); bsplit(v1.w, h[7], m[7], l[7]);
            uint32_t soff = abase + (((uint32_t)(kl * 2)) ^ aswz);
            *(uint4*)(bufp + TB_AH + soff) =
                make_uint4(hpack(h[0],h[1]), hpack(h[2],h[3]),
                           hpack(h[4],h[5]), hpack(h[6],h[7]));
            *(uint4*)(bufp + TB_AM + soff) =
                make_uint4(hpack(m[0],m[1]), hpack(m[2],m[3]),
                           hpack(m[4],m[5]), hpack(m[6],m[7]));
            *(uint4*)(bufp + TB_AL + soff) =
                make_uint4(hpack(l[0],l[1]), hpack(l[2],l[3]),
                           hpack(l[4],l[5]), hpack(l[6],l[7]));
        }
    };

    ldA(0);
    cpB(0, sbase);
    stsA(smg);
    asm volatile("cp.async.wait_group 0;" ::: "memory");
    __syncthreads();

    for (int kt = 0; kt < NKT; kt++) {
        const uint32_t cbuf = (uint32_t)(kt & 1) * TB_SIZE;
        const uint32_t nbuf = (uint32_t)((kt + 1) & 1) * TB_SIZE;

        if (kt + 1 < NKT) {
            ldA(kt + 1);
            cpB(kt + 1, sbase + nbuf);
        }

        #pragma unroll
        for (int ks = 0; ks < 4; ks++) {
            const int kb = ks * 16;
            uint32_t ah[4][4], am[4][4], bh[4][2], bm[4][2];

            #pragma unroll
            for (int mt = 0; mt < 4; mt++) {
                uint32_t row = (uint32_t)(mw * 64 + mt * 16 + ra);
                uint32_t off = row * 128 + (((uint32_t)((kb + ka) * 2)) ^ lswz);
                ldsm4(ah[mt], sbase + cbuf + TB_AH + off);
                ldsm4(am[mt], sbase + cbuf + TB_AM + off);
            }
            #pragma unroll
            for (int g = 0; g < 2; g++) {
                uint32_t row = (uint32_t)(nw * 32 + g * 16 + rb);
                uint32_t off = row * 128 + (((uint32_t)((kb + kbl) * 2)) ^ lswz);
                uint32_t r4[4];
                ldsm4(r4, sbase + cbuf + TB_BH + off);
                bh[g*2][0] = r4[0]; bh[g*2][1] = r4[1];
                bh[g*2+1][0] = r4[2]; bh[g*2+1][1] = r4[3];
                ldsm4(r4, sbase + cbuf + TB_BM + off);
                bm[g*2][0] = r4[0]; bm[g*2][1] = r4[1];
                bm[g*2+1][0] = r4[2]; bm[g*2+1][1] = r4[3];
            }
            #pragma unroll
            for (int mt = 0; mt < 4; mt++)
                #pragma unroll
                for (int nt = 0; nt < 4; nt++) {
                    mma_bf16(acc[mt][nt], am[mt], bm[nt]);   // mm
                    mma_bf16(acc[mt][nt], ah[mt], bm[nt]);   // hm
                }
            #pragma unroll
            for (int g = 0; g < 2; g++) {
                uint32_t row = (uint32_t)(nw * 32 + g * 16 + rb);
                uint32_t off = row * 128 + (((uint32_t)((kb + kbl) * 2)) ^ lswz);
                uint32_t r4[4];
                ldsm4(r4, sbase + cbuf + TB_BL + off);
                bm[g*2][0] = r4[0]; bm[g*2][1] = r4[1];
                bm[g*2+1][0] = r4[2]; bm[g*2+1][1] = r4[3];
            }
            #pragma unroll
            for (int mt = 0; mt < 4; mt++)
                #pragma unroll
                for (int nt = 0; nt < 4; nt++)
                    mma_bf16(acc[mt][nt], am[mt], bh[nt]);   // mh
            #pragma unroll
            for (int mt = 0; mt < 4; mt++) {
                uint32_t row = (uint32_t)(mw * 64 + mt * 16 + ra);
                uint32_t off = row * 128 + (((uint32_t)((kb + ka) * 2)) ^ lswz);
                ldsm4(am[mt], sbase + cbuf + TB_AL + off);
            }
            #pragma unroll
            for (int mt = 0; mt < 4; mt++)
                #pragma unroll
                for (int nt = 0; nt < 4; nt++) {
                    mma_bf16(acc[mt][nt], ah[mt], bm[nt]);   // hl
                    mma_bf16(acc[mt][nt], am[mt], bh[nt]);   // lh
                    mma_bf16(acc[mt][nt], ah[mt], bh[nt]);   // hh
                }
        }

        if (kt + 1 < NKT) {
            stsA(smg + nbuf);
            asm volatile("cp.async.wait_group 0;" ::: "memory");
            __syncthreads();
        }
    }

    const float* sb1 = (const float*)(smg + GS_BIAS);
    const int r_lo = lane >> 2;
    const int c_lo = (lane & 3) * 2;
    #pragma unroll
    for (int mt = 0; mt < 4; mt++) {
        #pragma unroll
        for (int half = 0; half < 2; half++) {
            int mrow = m0 + mw * 64 + mt * 16 + r_lo + half * 8;
            int b = mrow / Tsz;
            int t = mrow - b * Tsz;
            float* orow = g_h1 + (size_t)t * (Bsz * Hd) + b * Hd;
            #pragma unroll
            for (int nt = 0; nt < 4; nt++) {
                int c = nw * 32 + nt * 8 + c_lo;
                float2 v;
                v.x = acc[mt][nt][half * 2 + 0] + sb1[c];
                v.y = acc[mt][nt][half * 2 + 1] + sb1[c + 1];
                *(float2*)(orow + c) = v;
            }
        }
    }
}

// ---------------------------------------------------------------------------
// Kernel 2: recurrent LIF — ONE WARP PER SAMPLE, 4 neurons/thread (j=4t..4t+3).
// Spike masks via 4 ballots per layer (bit t of word c <-> neuron 4t+c).
// ZERO barriers in the time loop; gathers are LDS.128 (4 cols at once).
// 128 CTAs; 256 threads load weights, then warps 0-1 run samples, rest exit.
// ---------------------------------------------------------------------------
#define SM_W0   0
#define SM_W1   16384
#define SM_W2   32768
#define SM_W3   49152
#define SM_RCB1 51712
#define SM_B2C  51840
#define SM_FLOATS 51968
#define SM_BYTES  (SM_FLOATS * 4)

__global__ void __launch_bounds__(256, 1) rec_kernel(
    const float* __restrict__ rcW1, const float* __restrict__ rcb1,
    const float* __restrict__ W2,   const float* __restrict__ b2,
    const float* __restrict__ rcW2, const float* __restrict__ rcb2,
    const float* __restrict__ W3,   const float* __restrict__ b3,
    float* __restrict__ out)
{
    extern __shared__ float sm[];
    float* sW0   = sm + SM_W0;
    float* sW1   = sm + SM_W1;
    float* sW2   = sm + SM_W2;
    float* sW3   = sm + SM_W3;
    float* srcb1 = sm + SM_RCB1;
    float* sb2c  = sm + SM_B2C;

    const int tid = threadIdx.x;

    {
        const float4* a = (const float4*)rcW1;
        const float4* c = (const float4*)W2;
        const float4* d = (const float4*)rcW2;
        float4* o0 = (float4*)sW0; float4* o1 = (float4*)sW1; float4* o2 = (float4*)sW2;
        for (int i = tid; i < (Hd * Hd) / 4; i += 256) {
            o0[i] = a[i]; o1[i] = c[i]; o2[i] = d[i];
        }
    }
    for (int i = tid; i < Hd * DOUT; i += 256) sW3[i] = W3[i];
    if (tid < Hd) {
        srcb1[tid] = rcb1[tid];
        sb2c[tid]  = b2[tid] + rcb2[tid];
    }
    __syncthreads();

    const int wid  = tid >> 5;
    if (wid >= 2) return;                 // only warps 0,1 run the recurrence

    const int lane = tid & 31;
    const int b    = blockIdx.x * 2 + wid;
    const int j0   = lane * 4;            // this thread's 4 neurons: j0..j0+3

    // per-thread constants
    const float4 rcb1_r = *(const float4*)(srcb1 + j0);
    const float4 b2c_r  = *(const float4*)(sb2c + j0);

    float4 v1 = make_float4(0.f, 0.f, 0.f, 0.f);
    float4 v2 = make_float4(0.f, 0.f, 0.f, 0.f);
    float  acc = 0.f;
    unsigned m1[4] = {0u,0u,0u,0u};       // word c: bit t <-> neuron 4t+c
    unsigned m2[4] = {0u,0u,0u,0u};

    const float* h1p = g_h1 + b * Hd + j0;
    float4 h1v = *(const float4*)h1p;

    const float* sW0j = sW0 + j0;
    const float* sW1j = sW1 + j0;
    const float* sW2j = sW2 + j0;

    for (int t = 0; t < Tsz; t++) {
        float4 h1n = (t + 1 < Tsz)
            ? *(const float4*)(h1p + (size_t)(t + 1) * (Bsz * Hd))
            : make_float4(0.f, 0.f, 0.f, 0.f);

        // ---- phase 1: u = h1 + rcb1 + y1_old @ rcW1 ----
        float4 u;
        u.x = h1v.x + rcb1_r.x; u.y = h1v.y + rcb1_r.y;
        u.z = h1v.z + rcb1_r.z; u.w = h1v.w + rcb1_r.w;
        #pragma unroll
        for (int c = 0; c < 4; c++) {
            unsigned mm = m1[c];
            while (mm) {
                int bit = __ffs(mm) - 1; mm &= mm - 1u;
                float4 w = *(const float4*)(sW0j + ((bit << 2) | c) * Hd);
                u.x += w.x; u.y += w.y; u.z += w.z; u.w += w.w;
            }
        }
        // LIF 1: v += (u - v)/2 ; spike >= 1 ; hard reset
        v1.x += (u.x - v1.x) * 0.5f;  v1.y += (u.y - v1.y) * 0.5f;
        v1.z += (u.z - v1.z) * 0.5f;  v1.w += (u.w - v1.w) * 0.5f;
        bool s0 = v1.x >= 1.f, s1b = v1.y >= 1.f, s2b = v1.z >= 1.f, s3 = v1.w >= 1.f;
        if (s0) v1.x = 0.f;  if (s1b) v1.y = 0.f;
        if (s2b) v1.z = 0.f; if (s3) v1.w = 0.f;
        m1[0] = __ballot_sync(0xffffffffu, s0);
        m1[1] = __ballot_sync(0xffffffffu, s1b);
        m1[2] = __ballot_sync(0xffffffffu, s2b);
        m1[3] = __ballot_sync(0xffffffffu, s3);

        // ---- phase 2: u2 = b2 + rcb2 + y1_new @ W2 + y2_old @ rcW2 ----
        float4 u2 = make_float4(b2c_r.x, b2c_r.y, b2c_r.z, b2c_r.w);
        #pragma unroll
        for (int c = 0; c < 4; c++) {
            unsigned mm = m1[c];
            while (mm) {
                int bit = __ffs(mm) - 1; mm &= mm - 1u;
                float4 w = *(const float4*)(sW1j + ((bit << 2) | c) * Hd);
                u2.x += w.x; u2.y += w.y; u2.z += w.z; u2.w += w.w;
            }
        }
        #pragma unroll
        for (int c = 0; c < 4; c++) {
            unsigned mm = m2[c];
            while (mm) {
                int bit = __ffs(mm) - 1; mm &= mm - 1u;
                float4 w = *(const float4*)(sW2j + ((bit << 2) | c) * Hd);
                u2.x += w.x; u2.y += w.y; u2.z += w.z; u2.w += w.w;
            }
        }
        // LIF 2
        v2.x += (u2.x - v2.x) * 0.5f;  v2.y += (u2.y - v2.y) * 0.5f;
        v2.z += (u2.z - v2.z) * 0.5f;  v2.w += (u2.w - v2.w) * 0.5f;
        s0 = v2.x >= 1.f; s1b = v2.y >= 1.f; s2b = v2.z >= 1.f; s3 = v2.w >= 1.f;
        if (s0) v2.x = 0.f;  if (s1b) v2.y = 0.f;
        if (s2b) v2.z = 0.f; if (s3) v2.w = 0.f;
        m2[0] = __ballot_sync(0xffffffffu, s0);
        m2[1] = __ballot_sync(0xffffffffu, s1b);
        m2[2] = __ballot_sync(0xffffffffu, s2b);
        m2[3] = __ballot_sync(0xffffffffu, s3);

        // ---- readout: acc += y2_new @ W3 (lanes 0..19, one out col each) ----
        if (lane < DOUT) {
            float a = 0.f;
            #pragma unroll
            for (int c = 0; c < 4; c++) {
                unsigned mm = m2[c];
                while (mm) {
                    int bit = __ffs(mm) - 1; mm &= mm - 1u;
                    a += sW3[((bit << 2) | c) * DOUT + lane];
                }
            }
            acc += a;
        }
        h1v = h1n;
    }

    if (lane < DOUT)
        out[b * DOUT + lane] = acc + (float)Tsz * b3[lane];
}

// ---------------------------------------------------------------------------
// Launch
// ---------------------------------------------------------------------------
extern "C" void kernel_launch(void* const* d_in, const int* in_sizes, int n_in,
                              void* d_out, int out_size)
{
    const float* x    = (const float*)d_in[0];
    const float* W1   = (const float*)d_in[1];
    const float* b1   = (const float*)d_in[2];
    const float* rcW1 = (const float*)d_in[3];
    const float* rcb1 = (const float*)d_in[4];
    const float* W2   = (const float*)d_in[5];
    const float* b2   = (const float*)d_in[6];
    const float* rcW2 = (const float*)d_in[7];
    const float* rcb2 = (const float*)d_in[8];
    const float* W3   = (const float*)d_in[9];
    const float* b3   = (const float*)d_in[10];
    float* out = (float*)d_out;

    cudaFuncSetAttribute(gemm1_kernel,
                         cudaFuncAttributeMaxDynamicSharedMemorySize, GS_BYTES);
    cudaFuncSetAttribute(rec_kernel,
                         cudaFuncAttributeMaxDynamicSharedMemorySize, SM_BYTES);

    // 0) split W1 into bf16 h/m/l tiles
    prep_kernel<<<(NKT * 128 * KT + 255) / 256, 256>>>(W1);

    // 1) h1_all = x @ W1 + b1 (bf16x3 HMMA, double-buffered pipeline)
    gemm1_kernel<<<(Bsz * Tsz) / 128, 256, GS_BYTES>>>(x, b1);

    // 2) recurrent LIF loop (1 warp/sample, barrier-free, ballot masks)
    rec_kernel<<<Bsz / 2, 256, SM_BYTES>>>(rcW1, rcb1, W2, b2,
                                           rcW2, rcb2, W3, b3, out);
}